// round 6
// baseline (speedup 1.0000x reference)
#include <cuda_runtime.h>
#include <cuda_bf16.h>
#include <math.h>
#include <stdint.h>

#define NTOT 9633792
#define BATCH_STRIDE 301056
#define CHUNK 18816

__device__ float g_V[NTOT];
__device__ float g_F[NTOT];
__device__ float g_H[NTOT];
__device__ float g_O[NTOT];
// 11 split-images (Wv,Wf,W1 x {h,m,l}; W2 x {h,m}), each [96 co][48 kpairs] b32
__device__ unsigned g_Wb[11 * 4608];

__device__ __forceinline__ unsigned pk2(__nv_bfloat16 a, __nv_bfloat16 b) {
    return ((unsigned)__bfloat16_as_ushort(b) << 16) | __bfloat16_as_ushort(a);
}
__device__ __forceinline__ unsigned short spl(float v, int sp) {
    __nv_bfloat16 h = __float2bfloat16(v);
    if (sp == 0) return __bfloat16_as_ushort(h);
    float r1 = v - __bfloat162float(h);
    __nv_bfloat16 m = __float2bfloat16(r1);
    if (sp == 1) return __bfloat16_as_ushort(m);
    return __bfloat16_as_ushort(__float2bfloat16(r1 - __bfloat162float(m)));
}
__device__ __forceinline__ void mma_bf16(float* c, const unsigned* a,
                                         const unsigned* b) {
    asm volatile(
        "mma.sync.aligned.m16n8k16.row.col.f32.bf16.bf16.f32 "
        "{%0,%1,%2,%3}, {%4,%5,%6,%7}, {%8,%9}, {%0,%1,%2,%3};"
        : "+f"(c[0]), "+f"(c[1]), "+f"(c[2]), "+f"(c[3])
        : "r"(a[0]), "r"(a[1]), "r"(a[2]), "r"(a[3]), "r"(b[0]), "r"(b[1]));
}

// ---- weight prep: bf16 split terms, [co][kpair] b32-packed ----------------
__global__ void prep_w(const float* __restrict__ Wv, const float* __restrict__ Wf,
                       const float* __restrict__ W1, const float* __restrict__ W2)
{
    for (int i = blockIdx.x * 256 + threadIdx.x; i < 11 * 4608;
         i += gridDim.x * 256) {
        int img = i / 4608, rem = i - img * 4608;
        int r = rem / 48, p = rem - r * 48;
        const float* W; int sp;
        if (img < 9) { W = (img < 3) ? Wv : (img < 6) ? Wf : W1; sp = img % 3; }
        else         { W = W2; sp = img - 9; }
        float v0 = W[r * 96 + 2 * p], v1 = W[r * 96 + 2 * p + 1];
        g_Wb[i] = ((unsigned)spl(v1, sp) << 16) | spl(v0, sp);
    }
}

// ---- conv1x1 via mma.sync bf16 multi-split --------------------------------
// Y[b,co,s] = bias[co] + sum_k W[co,k] X[b,k,s].  Tile M=64 s, N=96 co, K=96.
// 256 thr = 8 warps: warp_m = wid&1 (32 rows), warp_n = wid>>1 (24 cols).
template<int NS>
__global__ void __launch_bounds__(256) conv_mma(
    const float* __restrict__ X, const unsigned* __restrict__ Wb,
    const float* __restrict__ bias, float* __restrict__ Y)
{
    extern __shared__ unsigned smemU[];
    unsigned* sA = smemU;                 // NS x [64 m][52 pairs]
    unsigned* sB = smemU + NS * 3328;     // NS x [96 co][52 pairs]
    float* sBias = (float*)(sB + NS * 4992);

    const int tid = threadIdx.x, lane = tid & 31, wid = tid >> 5;
    const int wm = wid & 1, wn = wid >> 1;
    const int s0 = blockIdx.x * 64, b = blockIdx.y;
    const float* Xb = X + (size_t)b * BATCH_STRIDE;

    if (tid < 96) sBias[tid] = bias[tid];

    // B splits -> smem (uint4, repitch 48 -> 52)
    {
        const uint4* src = (const uint4*)Wb;
        for (int i = tid; i < NS * 1152; i += 256) {
            int ss = i / 1152, rem = i - ss * 1152;
            int co = rem / 12, q = rem - co * 12;
            *(uint4*)&sB[ss * 4992 + co * 52 + q * 4] = src[i];
        }
    }
    // A tile: load fp32, split, pack k-pairs
    for (int i = tid; i < 64 * 48; i += 256) {
        int m = i & 63, p = i >> 6;
        int s = s0 + m;
        float v0 = Xb[(size_t)(2 * p) * 3136 + s];
        float v1 = Xb[(size_t)(2 * p + 1) * 3136 + s];
        __nv_bfloat16 h0 = __float2bfloat16(v0), h1 = __float2bfloat16(v1);
        sA[0 * 3328 + m * 52 + p] = pk2(h0, h1);
        float r0 = v0 - __bfloat162float(h0), r1 = v1 - __bfloat162float(h1);
        __nv_bfloat16 m0 = __float2bfloat16(r0), m1 = __float2bfloat16(r1);
        sA[1 * 3328 + m * 52 + p] = pk2(m0, m1);
        if (NS == 3)
            sA[2 * 3328 + m * 52 + p] =
                pk2(__float2bfloat16(r0 - __bfloat162float(m0)),
                    __float2bfloat16(r1 - __bfloat162float(m1)));
    }
    __syncthreads();

    float acc[2][3][4];
    #pragma unroll
    for (int mt = 0; mt < 2; mt++)
        #pragma unroll
        for (int nt = 0; nt < 3; nt++)
            #pragma unroll
            for (int q = 0; q < 4; q++) acc[mt][nt][q] = 0.f;

    const int g = lane >> 2, t = lane & 3;
    const int chA[6] = {0, 0, 1, 1, 0, 2}, chB[6] = {0, 1, 0, 1, 2, 0};
    const int NCH = (NS == 3) ? 6 : 3;

    for (int kt = 0; kt < 6; kt++) {
        int pb = kt * 8 + t;
        unsigned a[NS][2][4], bf[NS][3][2];
        #pragma unroll
        for (int sp = 0; sp < NS; sp++) {
            #pragma unroll
            for (int mt = 0; mt < 2; mt++) {
                int rm = wm * 32 + mt * 16 + g;
                a[sp][mt][0] = sA[sp * 3328 + rm * 52 + pb];
                a[sp][mt][1] = sA[sp * 3328 + (rm + 8) * 52 + pb];
                a[sp][mt][2] = sA[sp * 3328 + rm * 52 + pb + 4];
                a[sp][mt][3] = sA[sp * 3328 + (rm + 8) * 52 + pb + 4];
            }
            #pragma unroll
            for (int nt = 0; nt < 3; nt++) {
                int co = wn * 24 + nt * 8 + g;
                bf[sp][nt][0] = sB[sp * 4992 + co * 52 + pb];
                bf[sp][nt][1] = sB[sp * 4992 + co * 52 + pb + 4];
            }
        }
        #pragma unroll
        for (int c = 0; c < NCH; c++)
            #pragma unroll
            for (int mt = 0; mt < 2; mt++)
                #pragma unroll
                for (int nt = 0; nt < 3; nt++)
                    mma_bf16(acc[mt][nt], a[chA[c]][mt], bf[chB[c]][nt]);
    }

    // epilogue: Y[co][s] scattered b32 stores (32B-sector friendly)
    float* Yb = Y + (size_t)b * BATCH_STRIDE;
    #pragma unroll
    for (int mt = 0; mt < 2; mt++) {
        int sA0 = s0 + wm * 32 + mt * 16 + g;
        #pragma unroll
        for (int nt = 0; nt < 3; nt++) {
            int c0 = wn * 24 + nt * 8 + t * 2;
            float b0 = sBias[c0], b1 = sBias[c0 + 1];
            Yb[(size_t)c0 * 3136 + sA0]           = acc[mt][nt][0] + b0;
            Yb[(size_t)(c0 + 1) * 3136 + sA0]     = acc[mt][nt][1] + b1;
            Yb[(size_t)c0 * 3136 + sA0 + 8]       = acc[mt][nt][2] + b0;
            Yb[(size_t)(c0 + 1) * 3136 + sA0 + 8] = acc[mt][nt][3] + b1;
        }
    }
}

// ---- clustering: 256 thr, small smem, gmem/L2-resident --------------------
__global__ void __launch_bounds__(256) cluster_kernel(
    const float* __restrict__ Vg, const float* __restrict__ Fg,
    const float* __restrict__ Hg, const float* __restrict__ Wc,
    const float* __restrict__ bc, const float* __restrict__ alphap,
    const float* __restrict__ betap, float* __restrict__ Og)
{
    __shared__ float sSim0[4 * 784];
    __shared__ float sSimVal[784];
    __shared__ int   sAmax[784];
    __shared__ float sPoolH[96], sPoolF[96], sC1[96], sC2[96];
    __shared__ __align__(16) float sOutC[96];
    __shared__ float sP3[8][25];
    __shared__ float sCN[4][24];
    __shared__ float sNorm[4];
    __shared__ int   sCnt[4];

    const int B = blockIdx.x, tid = threadIdx.x;
    const int lane = tid & 31, wid = tid >> 5;
    const float* Vw = Vg + (size_t)B * CHUNK;
    const float* Fw = Fg + (size_t)B * CHUNK;
    const float* Hw = Hg + (size_t)B * CHUNK;
    float*       Ow = Og + (size_t)B * CHUNK;

    if (tid < 4) sCnt[tid] = 0;

    if (tid < 192) {  // 2x2 adaptive pool of H and F
        int arr = tid >= 96, idx = arr ? tid - 96 : tid;
        int c2 = idx >> 2, pos = idx & 3;
        const float* src = (arr ? Fw : Hw)
                         + c2 * 784 + (pos >> 1) * 14 * 28 + (pos & 1) * 14;
        float sum = 0.f;
        for (int rr = 0; rr < 14; rr++)
            #pragma unroll
            for (int cc = 0; cc < 14; cc++) sum += src[rr * 28 + cc];
        float v = sum * (1.f / 196.f);
        if (arr) sPoolF[idx] = v; else sPoolH[idx] = v;
    }
    __syncthreads();

    if (tid < 96) {   // centers1 = Wc @ pooledH + bc  (flat [m*24+ch])
        int o = tid >> 2, pos = tid & 3;
        float a = bc[o];
        #pragma unroll
        for (int k = 0; k < 24; k++)
            a = fmaf(Wc[o * 24 + k], sPoolH[k * 4 + pos], a);
        sC1[tid] = a;
    }
    __syncthreads();

    for (int n = tid; n < 784; n += 256) {   // sim0 = softmax_m(c1 . v)
        const float4* vp = (const float4*)(Vw + n * 24);
        float v[24];
        #pragma unroll
        for (int q = 0; q < 6; q++) {
            float4 t = vp[q];
            v[q*4]=t.x; v[q*4+1]=t.y; v[q*4+2]=t.z; v[q*4+3]=t.w;
        }
        float d[4];
        #pragma unroll
        for (int m = 0; m < 4; m++) {
            float a = 0.f;
            #pragma unroll
            for (int k = 0; k < 24; k++) a = fmaf(sC1[m * 24 + k], v[k], a);
            d[m] = a;
        }
        float mx = fmaxf(fmaxf(d[0], d[1]), fmaxf(d[2], d[3]));
        float e0 = expf(d[0]-mx), e1 = expf(d[1]-mx),
              e2 = expf(d[2]-mx), e3 = expf(d[3]-mx);
        float inv = 1.f / (e0 + e1 + e2 + e3);
        sSim0[n] = e0*inv; sSim0[784+n] = e1*inv;
        sSim0[1568+n] = e2*inv; sSim0[2352+n] = e3*inv;
    }
    __syncthreads();

    {   // centers2[m][ch] = sum_n sim0*F ; warp=(m,seg of 392), lane=ch
        int m = wid & 3, seg = wid >> 2;
        if (lane < 24) {
            float a = 0.f;
            for (int n = seg * 392; n < seg * 392 + 392; n++)
                a = fmaf(sSim0[m * 784 + n], Fw[n * 24 + lane], a);
            sP3[wid][lane] = a;
        }
    }
    __syncthreads();
    if (tid < 96) {
        int m = tid / 24, ch = tid - m * 24;
        sC2[tid] = sP3[m][ch] + sP3[4 + m][ch];
    }
    __syncthreads();

    if (tid < 4) {    // cn norms (cn[m][c2] = C2flat[c2*4+m])
        float s = 0.f;
        #pragma unroll
        for (int c2 = 0; c2 < 24; c2++) { float v = sC2[c2*4+tid]; s += v*v; }
        sNorm[tid] = fmaxf(sqrtf(s), 1e-12f);
    }
    __syncthreads();
    if (tid < 96) {
        int m = tid / 24, c2 = tid - m * 24;
        sCN[m][c2] = sC2[c2 * 4 + m] / sNorm[m];
    }
    __syncthreads();

    const float alpha = *alphap, beta = *betap;
    for (int it = 0; it < 4; it++) {   // cosine -> sigmoid -> first argmax
        int n = tid + it * 256;
        bool act = n < 784;
        int bi = -1;
        if (act) {
            float ns = 0.f, a0 = 0.f, a1 = 0.f, a2 = 0.f, a3 = 0.f;
            #pragma unroll
            for (int c2 = 0; c2 < 24; c2++) {
                float v = Hw[c2 * 784 + n];
                ns = fmaf(v, v, ns);
                a0 = fmaf(sCN[0][c2], v, a0); a1 = fmaf(sCN[1][c2], v, a1);
                a2 = fmaf(sCN[2][c2], v, a2); a3 = fmaf(sCN[3][c2], v, a3);
            }
            float inv = 1.f / fmaxf(sqrtf(ns), 1e-12f);
            float am[4] = {a0, a1, a2, a3};
            float best = -1.f; bi = 0;
            #pragma unroll
            for (int m = 0; m < 4; m++) {
                float sg = 1.f / (1.f + expf(-(beta + alpha * (am[m] * inv))));
                if (sg > best) { best = sg; bi = m; }
            }
            sSimVal[n] = best; sAmax[n] = bi;
        }
        #pragma unroll
        for (int m = 0; m < 4; m++) {
            unsigned bm = __ballot_sync(0xffffffffu, act && (bi == m));
            if (lane == 0 && bm) atomicAdd(&sCnt[m], __popc(bm));
        }
    }
    __syncthreads();

    {   // masked aggregation
        int m = wid & 3, seg = wid >> 2;
        if (lane < 24) {
            float a = 0.f;
            for (int n = seg * 392; n < seg * 392 + 392; n++)
                if (sAmax[n] == m) a = fmaf(sSimVal[n], Fw[n * 24 + lane], a);
            sP3[wid][lane] = a;
        }
    }
    __syncthreads();
    if (tid < 96) {
        int m = tid / 24, ch = tid - m * 24;
        sOutC[tid] = (sP3[m][ch] + sP3[4 + m][ch] + sPoolF[tid])
                     / ((float)sCnt[m] + 1.f);
    }
    __syncthreads();

    {   // broadcast back to tokens
        float4* o4 = (float4*)Ow;
        const float4* c4 = (const float4*)sOutC;
        for (int n = tid; n < 784; n += 256) {
            int a = sAmax[n];
            float sv = sSimVal[n];
            #pragma unroll
            for (int q = 0; q < 6; q++) {
                float4 t = c4[a * 6 + q];
                t.x *= sv; t.y *= sv; t.z *= sv; t.w *= sv;
                o4[n * 6 + q] = t;
            }
        }
    }
}

// ---------------------------------------------------------------------------
extern "C" void kernel_launch(void* const* d_in, const int* in_sizes, int n_in,
                              void* d_out, int out_size)
{
    const float* x  = (const float*)d_in[0];
    const float* Wv = (const float*)d_in[1];
    const float* bv = (const float*)d_in[2];
    const float* Wf = (const float*)d_in[3];
    const float* bf = (const float*)d_in[4];
    const float* W1 = (const float*)d_in[5];
    const float* b1 = (const float*)d_in[6];
    const float* Wc = (const float*)d_in[7];
    const float* bc = (const float*)d_in[8];
    const float* W2 = (const float*)d_in[9];
    const float* b2 = (const float*)d_in[10];
    const float* sa = (const float*)d_in[11];
    const float* sb = (const float*)d_in[12];
    float* out = (float*)d_out;

    float *V, *F, *H, *O; unsigned* Wb;
    cudaGetSymbolAddress((void**)&V, g_V);
    cudaGetSymbolAddress((void**)&F, g_F);
    cudaGetSymbolAddress((void**)&H, g_H);
    cudaGetSymbolAddress((void**)&O, g_O);
    cudaGetSymbolAddress((void**)&Wb, g_Wb);

    const int sm3 = (3 * 3328 + 3 * 4992) * 4 + 512;
    const int sm2 = (2 * 3328 + 2 * 4992) * 4 + 512;
    cudaFuncSetAttribute(conv_mma<3>, cudaFuncAttributeMaxDynamicSharedMemorySize, sm3);
    cudaFuncSetAttribute(conv_mma<2>, cudaFuncAttributeMaxDynamicSharedMemorySize, sm2);

    prep_w<<<33, 256>>>(Wv, Wf, W1, W2);
    dim3 grid(49, 32);
    conv_mma<3><<<grid, 256, sm3>>>(x, Wb + 0 * 4608, bv, V);
    conv_mma<3><<<grid, 256, sm3>>>(x, Wb + 3 * 4608, bf, F);
    conv_mma<3><<<grid, 256, sm3>>>(x, Wb + 6 * 4608, b1, H);
    cluster_kernel<<<512, 256>>>(V, F, H, Wc, bc, sa, sb, O);
    conv_mma<2><<<grid, 256, sm2>>>(O, Wb + 9 * 4608, b2, out);
}

// round 7
// speedup vs baseline: 1.4008x; 1.4008x over previous
#include <cuda_runtime.h>
#include <cuda_bf16.h>
#include <math.h>
#include <stdint.h>

#define NTOT 9633792
#define BATCH_STRIDE 301056
#define CHUNK 18816

__device__ float g_V[NTOT];
__device__ float g_F[NTOT];
__device__ float g_H[NTOT];
__device__ float g_O[NTOT];
// 11 fragment images (Wv,Wf,W1 x {h,m,l}; W2 x {h,m}).
// Layout per image: [nb(12)][kb(6)][lane(32)][j(2)] u32  (= mma B operand regs)
__device__ unsigned g_Wb[11 * 4608];

__device__ __forceinline__ unsigned pk2(__nv_bfloat16 a, __nv_bfloat16 b) {
    return ((unsigned)__bfloat16_as_ushort(b) << 16) | __bfloat16_as_ushort(a);
}
__device__ __forceinline__ unsigned short spl(float v, int sp) {
    __nv_bfloat16 h = __float2bfloat16(v);
    if (sp == 0) return __bfloat16_as_ushort(h);
    float r1 = v - __bfloat162float(h);
    __nv_bfloat16 m = __float2bfloat16(r1);
    if (sp == 1) return __bfloat16_as_ushort(m);
    return __bfloat16_as_ushort(__float2bfloat16(r1 - __bfloat162float(m)));
}
__device__ __forceinline__ void mma_bf16(float* c, const unsigned* a,
                                         const unsigned* b) {
    asm volatile(
        "mma.sync.aligned.m16n8k16.row.col.f32.bf16.bf16.f32 "
        "{%0,%1,%2,%3}, {%4,%5,%6,%7}, {%8,%9}, {%0,%1,%2,%3};"
        : "+f"(c[0]), "+f"(c[1]), "+f"(c[2]), "+f"(c[3])
        : "r"(a[0]), "r"(a[1]), "r"(a[2]), "r"(a[3]), "r"(b[0]), "r"(b[1]));
}
__device__ __forceinline__ void ldsm4(unsigned* r, unsigned addr) {
    asm volatile("ldmatrix.sync.aligned.m8n8.x4.shared.b16 {%0,%1,%2,%3}, [%4];"
                 : "=r"(r[0]), "=r"(r[1]), "=r"(r[2]), "=r"(r[3]) : "r"(addr));
}
__device__ __forceinline__ unsigned su32(const void* p) {
    unsigned r;
    asm("{ .reg .u64 t; cvta.to.shared.u64 t, %1; cvt.u32.u64 %0, t; }"
        : "=r"(r) : "l"(p));
    return r;
}

// ---- weight prep: bf16 split terms as ready-made B mma fragments ----------
__global__ void prep_w(const float* __restrict__ Wv, const float* __restrict__ Wf,
                       const float* __restrict__ W1, const float* __restrict__ W2)
{
    for (int i = blockIdx.x * 256 + threadIdx.x; i < 11 * 4608;
         i += gridDim.x * 256) {
        int img = i / 4608, rem = i - img * 4608;
        int nb = rem / 384, r2 = rem - nb * 384;
        int kb = r2 / 64, l2 = r2 - kb * 64;
        int lane = l2 >> 1, j = l2 & 1;
        int g = lane >> 2, t = lane & 3;
        int co = nb * 8 + g;
        int kp = kb * 8 + t + j * 4;          // k-pair index
        const float* W; int sp;
        if (img < 9) { W = (img < 3) ? Wv : (img < 6) ? Wf : W1; sp = img % 3; }
        else         { W = W2; sp = img - 9; }
        float v0 = W[co * 96 + 2 * kp], v1 = W[co * 96 + 2 * kp + 1];
        g_Wb[i] = ((unsigned)spl(v1, sp) << 16) | spl(v0, sp);
    }
}

// ---- conv1x1 via mma.sync bf16 multi-split, v2 ----------------------------
// Tile M=128 s x N=96 co x K=96. 8 warps = 4m x 2n. A in smem (ldmatrix),
// B operands fetched as pre-baked fragments via coalesced L1-resident LDG.64.
// smem A pitch 208B -> conflict-free LDSM phases.
template<int NS>
__global__ void __launch_bounds__(256, 2) conv_mma(
    const float* __restrict__ X, const unsigned* __restrict__ Wb,
    const float* __restrict__ bias, float* __restrict__ Y)
{
    extern __shared__ unsigned smemU[];           // NS x [128 m][52 u32]
    const int tid = threadIdx.x, lane = tid & 31, wid = tid >> 5;
    const int wm = wid & 3, wn = wid >> 2;
    const int g = lane >> 2, t = lane & 3;
    const int s0 = blockIdx.x * 128, b = blockIdx.y;
    const float* Xb = X + (size_t)b * BATCH_STRIDE;
    const uint2* Bf = (const uint2*)Wb;           // this conv's split-0 frags

    // A tile: load fp32 (coalesced), split to bf16 terms, pack k-pairs
    for (int i = tid; i < 128 * 48; i += 256) {
        int m = i & 127, p = i >> 7;
        int s = s0 + m;
        bool ok = s < 3136;
        float v0 = ok ? Xb[(size_t)(2 * p) * 3136 + s] : 0.f;
        float v1 = ok ? Xb[(size_t)(2 * p + 1) * 3136 + s] : 0.f;
        __nv_bfloat16 h0 = __float2bfloat16(v0), h1 = __float2bfloat16(v1);
        smemU[0 * 6656 + m * 52 + p] = pk2(h0, h1);
        float r0 = v0 - __bfloat162float(h0), r1 = v1 - __bfloat162float(h1);
        __nv_bfloat16 m0 = __float2bfloat16(r0), m1 = __float2bfloat16(r1);
        smemU[1 * 6656 + m * 52 + p] = pk2(m0, m1);
        if (NS == 3)
            smemU[2 * 6656 + m * 52 + p] =
                pk2(__float2bfloat16(r0 - __bfloat162float(m0)),
                    __float2bfloat16(r1 - __bfloat162float(m1)));
    }
    __syncthreads();

    float acc[2][6][4];
    #pragma unroll
    for (int mt = 0; mt < 2; mt++)
        #pragma unroll
        for (int nt = 0; nt < 6; nt++)
            #pragma unroll
            for (int q = 0; q < 4; q++) acc[mt][nt][q] = 0.f;

    // LDSM base address: row = wm*32 + (lane&15), col-half = lane>>4
    const unsigned abase = su32(smemU)
        + (unsigned)(wm * 32 + (lane & 15)) * 208 + (unsigned)(lane >> 4) * 16;

    const int chA[6] = {0, 0, 1, 1, 0, 2}, chB[6] = {0, 1, 0, 1, 2, 0};
    const int NCH = (NS == 3) ? 6 : 3;

    #pragma unroll
    for (int kt = 0; kt < 6; kt++) {
        unsigned a[NS][2][4];
        #pragma unroll
        for (int sp = 0; sp < NS; sp++)
            #pragma unroll
            for (int mt = 0; mt < 2; mt++)
                ldsm4(a[sp][mt],
                      abase + (unsigned)sp * 26624 + (unsigned)mt * 3328
                            + (unsigned)kt * 32);
        #pragma unroll
        for (int ng = 0; ng < 2; ng++) {
            uint2 bv[NS][3];
            #pragma unroll
            for (int sp = 0; sp < NS; sp++)
                #pragma unroll
                for (int nt = 0; nt < 3; nt++) {
                    int nb = wn * 6 + ng * 3 + nt;
                    bv[sp][nt] = Bf[(size_t)sp * 2304 + (nb * 6 + kt) * 32 + lane];
                }
            #pragma unroll
            for (int c = 0; c < NCH; c++)
                #pragma unroll
                for (int mt = 0; mt < 2; mt++)
                    #pragma unroll
                    for (int nt = 0; nt < 3; nt++)
                        mma_bf16(acc[mt][ng * 3 + nt], a[chA[c]][mt],
                                 (const unsigned*)&bv[chB[c]][nt]);
        }
    }

    // epilogue: Y[co][s] scatter
    float* Yb = Y + (size_t)b * BATCH_STRIDE;
    #pragma unroll
    for (int mt = 0; mt < 2; mt++) {
        int sr = s0 + wm * 32 + mt * 16 + g;
        #pragma unroll
        for (int nt = 0; nt < 6; nt++) {
            int c0 = wn * 48 + nt * 8 + t * 2;
            float b0 = bias[c0], b1 = bias[c0 + 1];
            if (sr < 3136) {
                Yb[(size_t)c0 * 3136 + sr]       = acc[mt][nt][0] + b0;
                Yb[(size_t)(c0 + 1) * 3136 + sr] = acc[mt][nt][1] + b1;
            }
            if (sr + 8 < 3136) {
                Yb[(size_t)c0 * 3136 + sr + 8]       = acc[mt][nt][2] + b0;
                Yb[(size_t)(c0 + 1) * 3136 + sr + 8] = acc[mt][nt][3] + b1;
            }
        }
    }
}

// ---- clustering: 256 thr, small smem, gmem/L2-resident --------------------
__global__ void __launch_bounds__(256) cluster_kernel(
    const float* __restrict__ Vg, const float* __restrict__ Fg,
    const float* __restrict__ Hg, const float* __restrict__ Wc,
    const float* __restrict__ bc, const float* __restrict__ alphap,
    const float* __restrict__ betap, float* __restrict__ Og)
{
    __shared__ float sSim0[4 * 784];
    __shared__ float sSimVal[784];
    __shared__ int   sAmax[784];
    __shared__ float sPoolH[96], sPoolF[96], sC1[96], sC2[96];
    __shared__ __align__(16) float sOutC[96];
    __shared__ float sP3[8][25];
    __shared__ float sCN[4][24];
    __shared__ float sNorm[4];
    __shared__ int   sCnt[4];

    const int B = blockIdx.x, tid = threadIdx.x;
    const int lane = tid & 31, wid = tid >> 5;
    const float* Vw = Vg + (size_t)B * CHUNK;
    const float* Fw = Fg + (size_t)B * CHUNK;
    const float* Hw = Hg + (size_t)B * CHUNK;
    float*       Ow = Og + (size_t)B * CHUNK;

    if (tid < 4) sCnt[tid] = 0;

    if (tid < 192) {  // 2x2 adaptive pool of H and F
        int arr = tid >= 96, idx = arr ? tid - 96 : tid;
        int c2 = idx >> 2, pos = idx & 3;
        const float* src = (arr ? Fw : Hw)
                         + c2 * 784 + (pos >> 1) * 14 * 28 + (pos & 1) * 14;
        float sum = 0.f;
        for (int rr = 0; rr < 14; rr++)
            #pragma unroll
            for (int cc = 0; cc < 14; cc++) sum += src[rr * 28 + cc];
        float v = sum * (1.f / 196.f);
        if (arr) sPoolF[idx] = v; else sPoolH[idx] = v;
    }
    __syncthreads();

    if (tid < 96) {   // centers1 = Wc @ pooledH + bc  (flat [m*24+ch])
        int o = tid >> 2, pos = tid & 3;
        float a = bc[o];
        #pragma unroll
        for (int k = 0; k < 24; k++)
            a = fmaf(Wc[o * 24 + k], sPoolH[k * 4 + pos], a);
        sC1[tid] = a;
    }
    __syncthreads();

    for (int n = tid; n < 784; n += 256) {   // sim0 = softmax_m(c1 . v)
        const float4* vp = (const float4*)(Vw + n * 24);
        float v[24];
        #pragma unroll
        for (int q = 0; q < 6; q++) {
            float4 t = vp[q];
            v[q*4]=t.x; v[q*4+1]=t.y; v[q*4+2]=t.z; v[q*4+3]=t.w;
        }
        float d[4];
        #pragma unroll
        for (int m = 0; m < 4; m++) {
            float a = 0.f;
            #pragma unroll
            for (int k = 0; k < 24; k++) a = fmaf(sC1[m * 24 + k], v[k], a);
            d[m] = a;
        }
        float mx = fmaxf(fmaxf(d[0], d[1]), fmaxf(d[2], d[3]));
        float e0 = expf(d[0]-mx), e1 = expf(d[1]-mx),
              e2 = expf(d[2]-mx), e3 = expf(d[3]-mx);
        float inv = 1.f / (e0 + e1 + e2 + e3);
        sSim0[n] = e0*inv; sSim0[784+n] = e1*inv;
        sSim0[1568+n] = e2*inv; sSim0[2352+n] = e3*inv;
    }
    __syncthreads();

    {   // centers2[m][ch] = sum_n sim0*F ; warp=(m,seg of 392), lane=ch
        int m = wid & 3, seg = wid >> 2;
        if (lane < 24) {
            float a = 0.f;
            for (int n = seg * 392; n < seg * 392 + 392; n++)
                a = fmaf(sSim0[m * 784 + n], Fw[n * 24 + lane], a);
            sP3[wid][lane] = a;
        }
    }
    __syncthreads();
    if (tid < 96) {
        int m = tid / 24, ch = tid - m * 24;
        sC2[tid] = sP3[m][ch] + sP3[4 + m][ch];
    }
    __syncthreads();

    if (tid < 4) {    // cn norms (cn[m][c2] = C2flat[c2*4+m])
        float s = 0.f;
        #pragma unroll
        for (int c2 = 0; c2 < 24; c2++) { float v = sC2[c2*4+tid]; s += v*v; }
        sNorm[tid] = fmaxf(sqrtf(s), 1e-12f);
    }
    __syncthreads();
    if (tid < 96) {
        int m = tid / 24, c2 = tid - m * 24;
        sCN[m][c2] = sC2[c2 * 4 + m] / sNorm[m];
    }
    __syncthreads();

    const float alpha = *alphap, beta = *betap;
    for (int it = 0; it < 4; it++) {   // cosine -> sigmoid -> first argmax
        int n = tid + it * 256;
        bool act = n < 784;
        int bi = -1;
        if (act) {
            float ns = 0.f, a0 = 0.f, a1 = 0.f, a2 = 0.f, a3 = 0.f;
            #pragma unroll
            for (int c2 = 0; c2 < 24; c2++) {
                float v = Hw[c2 * 784 + n];
                ns = fmaf(v, v, ns);
                a0 = fmaf(sCN[0][c2], v, a0); a1 = fmaf(sCN[1][c2], v, a1);
                a2 = fmaf(sCN[2][c2], v, a2); a3 = fmaf(sCN[3][c2], v, a3);
            }
            float inv = 1.f / fmaxf(sqrtf(ns), 1e-12f);
            float am[4] = {a0, a1, a2, a3};
            float best = -1.f; bi = 0;
            #pragma unroll
            for (int m = 0; m < 4; m++) {
                float sg = 1.f / (1.f + expf(-(beta + alpha * (am[m] * inv))));
                if (sg > best) { best = sg; bi = m; }
            }
            sSimVal[n] = best; sAmax[n] = bi;
        }
        #pragma unroll
        for (int m = 0; m < 4; m++) {
            unsigned bm = __ballot_sync(0xffffffffu, act && (bi == m));
            if (lane == 0 && bm) atomicAdd(&sCnt[m], __popc(bm));
        }
    }
    __syncthreads();

    {   // masked aggregation
        int m = wid & 3, seg = wid >> 2;
        if (lane < 24) {
            float a = 0.f;
            for (int n = seg * 392; n < seg * 392 + 392; n++)
                if (sAmax[n] == m) a = fmaf(sSimVal[n], Fw[n * 24 + lane], a);
            sP3[wid][lane] = a;
        }
    }
    __syncthreads();
    if (tid < 96) {
        int m = tid / 24, ch = tid - m * 24;
        sOutC[tid] = (sP3[m][ch] + sP3[4 + m][ch] + sPoolF[tid])
                     / ((float)sCnt[m] + 1.f);
    }
    __syncthreads();

    {   // broadcast back to tokens
        float4* o4 = (float4*)Ow;
        const float4* c4 = (const float4*)sOutC;
        for (int n = tid; n < 784; n += 256) {
            int a = sAmax[n];
            float sv = sSimVal[n];
            #pragma unroll
            for (int q = 0; q < 6; q++) {
                float4 t = c4[a * 6 + q];
                t.x *= sv; t.y *= sv; t.z *= sv; t.w *= sv;
                o4[n * 6 + q] = t;
            }
        }
    }
}

// ---------------------------------------------------------------------------
extern "C" void kernel_launch(void* const* d_in, const int* in_sizes, int n_in,
                              void* d_out, int out_size)
{
    const float* x  = (const float*)d_in[0];
    const float* Wv = (const float*)d_in[1];
    const float* bv = (const float*)d_in[2];
    const float* Wf = (const float*)d_in[3];
    const float* bf = (const float*)d_in[4];
    const float* W1 = (const float*)d_in[5];
    const float* b1 = (const float*)d_in[6];
    const float* Wc = (const float*)d_in[7];
    const float* bc = (const float*)d_in[8];
    const float* W2 = (const float*)d_in[9];
    const float* b2 = (const float*)d_in[10];
    const float* sa = (const float*)d_in[11];
    const float* sb = (const float*)d_in[12];
    float* out = (float*)d_out;

    float *V, *F, *H, *O; unsigned* Wb;
    cudaGetSymbolAddress((void**)&V, g_V);
    cudaGetSymbolAddress((void**)&F, g_F);
    cudaGetSymbolAddress((void**)&H, g_H);
    cudaGetSymbolAddress((void**)&O, g_O);
    cudaGetSymbolAddress((void**)&Wb, g_Wb);

    const int sm3 = 3 * 6656 * 4;   // 79872 B
    const int sm2 = 2 * 6656 * 4;   // 53248 B
    cudaFuncSetAttribute(conv_mma<3>, cudaFuncAttributeMaxDynamicSharedMemorySize, sm3);
    cudaFuncSetAttribute(conv_mma<2>, cudaFuncAttributeMaxDynamicSharedMemorySize, sm2);

    prep_w<<<33, 256>>>(Wv, Wf, W1, W2);
    dim3 grid(25, 32);
    conv_mma<3><<<grid, 256, sm3>>>(x, Wb + 0 * 4608, bv, V);
    conv_mma<3><<<grid, 256, sm3>>>(x, Wb + 3 * 4608, bf, F);
    conv_mma<3><<<grid, 256, sm3>>>(x, Wb + 6 * 4608, b1, H);
    cluster_kernel<<<512, 256>>>(V, F, H, Wc, bc, sa, sb, O);
    conv_mma<2><<<grid, 256, sm2>>>(O, Wb + 9 * 4608, b2, out);
}